// round 6
// baseline (speedup 1.0000x reference)
#include <cuda_runtime.h>
#include <math.h>

#define TT  64
#define BB  16
#define II  512
#define HH  512
#define OO  512
#define NN  256
#define WD  64
#define RR  4
#define NIN 768
#define IFW 471
#define FEPS 1e-6f

// ---------------- persistent state (static device globals: allowed) -------------
__device__ float g_M [BB*NN*WD];      // memory (B,N,W)
__device__ float g_u [BB*NN];         // usage
__device__ float g_p [2][BB*NN];      // precedence, double-buffered by step parity
__device__ float g_ww[BB*NN];         // write weights
__device__ float g_L [BB*NN*NN];      // temporal link (B,N,N)  4MB
__device__ float g_rw[BB*RR*NN];      // read weights (B,R,N)
__device__ float g_rv[BB*RR*WD];      // read vectors (B, R*W)
// per-step temporaries
__device__ float g_h  [BB*HH];
__device__ float g_po [BB*OO];
__device__ float g_if [BB*IFW];
__device__ float g_fwd[BB*RR*NN];

__device__ __forceinline__ float sigm(float x){ return 1.f/(1.f+expf(-x)); }
__device__ __forceinline__ float oneplus(float x){ return 1.f + (x > 20.f ? x : log1pf(expf(x))); }
__device__ __forceinline__ float wredsum(float v){
    #pragma unroll
    for (int o=16;o;o>>=1) v += __shfl_down_sync(0xffffffffu, v, o);
    return v;
}

// ---------------- init (must run inside the graph each replay) ------------------
__global__ void k_init(){
    int i0 = blockIdx.x*blockDim.x + threadIdx.x;
    int st = gridDim.x*blockDim.x;
    for (int i=i0;i<BB*NN*NN;i+=st) g_L[i]=0.f;
    for (int i=i0;i<BB*NN*WD;i+=st) g_M[i]=1e-6f;
    for (int i=i0;i<BB*NN;i+=st){ g_u[i]=0.f; g_p[0][i]=0.f; g_p[1][i]=0.f; g_ww[i]=0.f; }
    for (int i=i0;i<BB*RR*NN;i+=st) g_rw[i]=0.f;
    for (int i=i0;i<BB*RR*WD;i+=st) g_rv[i]=0.f;
}

// ---------------- K1: h = relu([x_t, rv] @ W_hid + b) ---------------------------
// grid (4,16), 128 threads. One batch per block-row; column slice per block-col.
__global__ void k_hidden(const float* __restrict__ x, const float* __restrict__ Wh,
                         const float* __restrict__ bh, int t){
    int b = blockIdx.y, tid = threadIdx.x;
    __shared__ __align__(16) float s[NIN];
    const float* xp = x + (t*BB + b)*II;
    for (int k=tid;k<NIN;k+=128) s[k] = (k<II) ? xp[k] : g_rv[b*(RR*WD) + (k-II)];
    __syncthreads();
    int j = blockIdx.x*128 + tid;
    const float* Wc = Wh + j;
    float a0 = bh[j], a1=0.f, a2=0.f, a3=0.f;
    #pragma unroll 4
    for (int k=0;k<NIN;k+=4){
        float4 sv = *reinterpret_cast<const float4*>(&s[k]);
        a0 = fmaf(sv.x, Wc[(k+0)*HH], a0);
        a1 = fmaf(sv.y, Wc[(k+1)*HH], a1);
        a2 = fmaf(sv.z, Wc[(k+2)*HH], a2);
        a3 = fmaf(sv.w, Wc[(k+3)*HH], a3);
    }
    g_h[b*HH + j] = fmaxf((a0+a1)+(a2+a3), 0.f);
}

// ---------------- K2: pre_out = h@W_out ; iface = h@W_iface ---------------------
// grid (8,16), 128 threads; j<512 -> out, else iface column j-512 (<471).
__global__ void k_proj(const float* __restrict__ Wo, const float* __restrict__ Wi){
    int b = blockIdx.y, tid = threadIdx.x;
    __shared__ __align__(16) float s[HH];
    for (int k=tid;k<HH;k+=128) s[k] = g_h[b*HH + k];
    __syncthreads();
    int j = blockIdx.x*128 + tid;
    if (j < OO){
        const float* Wc = Wo + j;
        float a0=0.f,a1=0.f,a2=0.f,a3=0.f;
        #pragma unroll 4
        for (int k=0;k<HH;k+=4){
            float4 sv = *reinterpret_cast<const float4*>(&s[k]);
            a0 = fmaf(sv.x, Wc[(k+0)*OO], a0);
            a1 = fmaf(sv.y, Wc[(k+1)*OO], a1);
            a2 = fmaf(sv.z, Wc[(k+2)*OO], a2);
            a3 = fmaf(sv.w, Wc[(k+3)*OO], a3);
        }
        g_po[b*OO + j] = (a0+a1)+(a2+a3);
    } else {
        int jj = j - OO;
        if (jj < IFW){
            const float* Wc = Wi + jj;
            float a0=0.f,a1=0.f,a2=0.f,a3=0.f;
            #pragma unroll 4
            for (int k=0;k<HH;k+=4){
                float4 sv = *reinterpret_cast<const float4*>(&s[k]);
                a0 = fmaf(sv.x, Wc[(k+0)*IFW], a0);
                a1 = fmaf(sv.y, Wc[(k+1)*IFW], a1);
                a2 = fmaf(sv.z, Wc[(k+2)*IFW], a2);
                a3 = fmaf(sv.w, Wc[(k+3)*IFW], a3);
            }
            g_if[b*IFW + jj] = (a0+a1)+(a2+a3);
        }
    }
}

// ---------------- K3: gates, usage, sort/alloc, write weights, precedence -------
// grid 16 blocks x 256 threads (one block per batch; thread = slot).
__global__ __launch_bounds__(256) void k_control(int par){
    int b = blockIdx.x, tid = threadIdx.x;
    __shared__ float sk[256]; __shared__ int si[256];
    __shared__ float sc[256], sa[256], red[256], simL[256], wk_s[64];
    __shared__ float s_wkden;
    const float* ifc = g_if + b*IFW;

    // forget gates
    float fg0 = sigm(ifc[453]), fg1 = sigm(ifc[454]), fg2 = sigm(ifc[455]), fg3 = sigm(ifc[456]);
    // retention & usage (uses OLD ww, OLD rw)
    float u   = g_u [b*NN + tid];
    float wwo = g_ww[b*NN + tid];
    float ret = (1.f - fg0*g_rw[(b*RR+0)*NN+tid])
              * (1.f - fg1*g_rw[(b*RR+1)*NN+tid])
              * (1.f - fg2*g_rw[(b*RR+2)*NN+tid])
              * (1.f - fg3*g_rw[(b*RR+3)*NN+tid]);
    float un = (u + wwo - u*wwo) * ret;
    g_u[b*NN + tid] = un;

    if (tid < 64) wk_s[tid] = ifc[260 + tid];
    sk[tid] = un; si[tid] = tid;
    __syncthreads();

    // bitonic sort ascending by (key, index) — replicates stable argsort
    for (int k2=2;k2<=256;k2<<=1){
        for (int j2=k2>>1;j2>0;j2>>=1){
            int ixj = tid ^ j2;
            if (ixj > tid){
                bool up = ((tid & k2)==0);
                float a = sk[tid], c = sk[ixj];
                int   ia = si[tid], ic = si[ixj];
                bool agtc = (a > c) || (a==c && ia > ic);
                if (up == agtc){ sk[tid]=c; sk[ixj]=a; si[tid]=ic; si[ixj]=ia; }
            }
            __syncthreads();
        }
    }
    // exclusive cumprod of sorted usage (Hillis-Steele product scan)
    sc[tid] = sk[tid]; __syncthreads();
    for (int d=1; d<256; d<<=1){
        float v = (tid>=d) ? sc[tid-d] : 1.f;
        __syncthreads();
        sc[tid] *= v;
        __syncthreads();
    }
    float cp = (tid==0) ? 1.f : sc[tid-1];
    sa[si[tid]] = (1.f - sk[tid]) * cp;          // scatter allocation weights

    int wi = tid>>5, l = tid&31;
    if (wi==0){
        float w0 = wk_s[l], w1 = wk_s[l+32];
        float ss = wredsum(w0*w0 + w1*w1);
        if (l==0) s_wkden = sqrtf(ss) + FEPS;
    }
    // content write sim: warp-per-row over OLD M (coalesced)
    for (int p2=0;p2<32;p2++){
        int n = wi*32 + p2;
        const float* Mr = g_M + (b*NN + n)*WD;
        float m0 = Mr[l], m1 = Mr[l+32];
        float ns = m0*m0 + m1*m1;
        float dt = m0*wk_s[l] + m1*wk_s[l+32];
        ns = wredsum(ns); dt = wredsum(dt);
        if (l==0) simL[n] = dt / (sqrtf(ns) + FEPS);
    }
    __syncthreads();

    float wb = oneplus(ifc[324]);
    float logit = wb * simL[tid] / s_wkden;
    red[tid]=logit; __syncthreads();
    for (int s2=128;s2>0;s2>>=1){ if (tid<s2) red[tid]=fmaxf(red[tid],red[tid+s2]); __syncthreads(); }
    float mx = red[0]; __syncthreads();
    float e = expf(logit - mx);
    red[tid]=e; __syncthreads();
    for (int s2=128;s2>0;s2>>=1){ if (tid<s2) red[tid]+=red[tid+s2]; __syncthreads(); }
    float cw = e / red[0]; __syncthreads();

    float ag = sigm(ifc[457]), wg = sigm(ifc[458]);
    float wwn = wg * (ag*sa[tid] + (1.f-ag)*cw);
    g_ww[b*NN + tid] = wwn;

    red[tid]=wwn; __syncthreads();
    for (int s2=128;s2>0;s2>>=1){ if (tid<s2) red[tid]+=red[tid+s2]; __syncthreads(); }
    float S = red[0];
    float po = g_p[par][b*NN + tid];
    g_p[par^1][b*NN + tid] = (1.f - S)*po + wwn;   // new precedence (consumed next step)
}

// ---------------- K4: M update + in-place L update fused with fwd ---------------
// grid (32,16), 256 threads = 8 warps; warp = one L row; block covers 8 rows.
__global__ __launch_bounds__(256) void k_meml(int par){
    int b = blockIdx.y, n0 = blockIdx.x*8;
    int tid = threadIdx.x, wi = tid>>5, l = tid&31;
    const float* ifc = g_if + b*IFW;

    // memory update for rows [n0, n0+8)
    #pragma unroll
    for (int q=0;q<2;q++){
        int idx = tid + q*256;
        int n = n0 + (idx>>6), w = idx & 63;
        float wwn = g_ww[b*NN + n];
        float ev  = sigm(ifc[325 + w]);
        float wv  = ifc[389 + w];
        float m   = g_M[(b*NN + n)*WD + w];
        g_M[(b*NN + n)*WD + w] = m*(1.f - wwn*ev) + wwn*wv;
    }

    // link row update + fwd (uses OLD p, OLD rw, NEW ww)
    int n = n0 + wi;
    float wwn = g_ww[b*NN + n];
    float* Lr = g_L + (b*NN + n)*NN;
    const float* pw  = g_p[par] + b*NN;
    const float* wwp = g_ww + b*NN;
    const float* rwp = g_rw + b*RR*NN;
    float f0=0.f,f1=0.f,f2=0.f,f3=0.f;
    #pragma unroll
    for (int k=0;k<8;k++){
        int m = l + k*32;
        float lo = Lr[m];
        float ln = (1.f - wwn - wwp[m])*lo + wwn*pw[m];
        if (m == n) ln = 0.f;
        Lr[m] = ln;
        f0 = fmaf(ln, rwp[0*NN+m], f0);
        f1 = fmaf(ln, rwp[1*NN+m], f1);
        f2 = fmaf(ln, rwp[2*NN+m], f2);
        f3 = fmaf(ln, rwp[3*NN+m], f3);
    }
    f0=wredsum(f0); f1=wredsum(f1); f2=wredsum(f2); f3=wredsum(f3);
    if (l==0){
        g_fwd[(b*RR+0)*NN+n]=f0; g_fwd[(b*RR+1)*NN+n]=f1;
        g_fwd[(b*RR+2)*NN+n]=f2; g_fwd[(b*RR+3)*NN+n]=f3;
    }
}

// ---------------- K5: bwd, read content softmax, rw_new, rv_new -----------------
// grid 16 blocks x 256 threads (one block per batch; thread = slot).
__global__ __launch_bounds__(256) void k_read(){
    int b = blockIdx.x, tid = threadIdx.x;
    __shared__ float4 rw4[256];
    __shared__ float4 rk4[64];
    __shared__ float simL[4][256];
    __shared__ float red[256];
    __shared__ float s_rknd[4], s_rbv[4], s_rm[4][3];
    __shared__ float4 rwn4[256];
    const float* ifc = g_if + b*IFW;
    const float* rwp = g_rw + b*RR*NN;

    rw4[tid] = make_float4(rwp[tid], rwp[NN+tid], rwp[2*NN+tid], rwp[3*NN+tid]);
    if (tid < 64) rk4[tid] = make_float4(ifc[tid], ifc[64+tid], ifc[128+tid], ifc[192+tid]);
    __syncthreads();

    int wi = tid>>5, l = tid&31;
    if (wi==0){
        float4 a = rk4[l], c = rk4[l+32];
        float s0 = wredsum(a.x*a.x + c.x*c.x);
        float s1 = wredsum(a.y*a.y + c.y*c.y);
        float s2 = wredsum(a.z*a.z + c.z*c.z);
        float s3 = wredsum(a.w*a.w + c.w*c.w);
        if (l==0){
            s_rknd[0]=sqrtf(s0)+FEPS; s_rknd[1]=sqrtf(s1)+FEPS;
            s_rknd[2]=sqrtf(s2)+FEPS; s_rknd[3]=sqrtf(s3)+FEPS;
        }
    } else if (wi==1 && l<4){
        int r = l;
        s_rbv[r] = oneplus(ifc[256 + r]);
        float v0=ifc[459+3*r], v1=ifc[460+3*r], v2=ifc[461+3*r];
        float mx = fmaxf(v0, fmaxf(v1, v2));
        float e0=expf(v0-mx), e1=expf(v1-mx), e2=expf(v2-mx);
        float inv = 1.f/(e0+e1+e2);
        s_rm[r][0]=e0*inv; s_rm[r][1]=e1*inv; s_rm[r][2]=e2*inv;
    }

    // bwd: column scan of L_new (coalesced), OLD rw from smem
    float bw0=0.f,bw1=0.f,bw2=0.f,bw3=0.f;
    const float* Lb = g_L + b*NN*NN;
    #pragma unroll 4
    for (int m=0;m<NN;m++){
        float lv = Lb[m*NN + tid];
        float4 rw = rw4[m];
        bw0 = fmaf(lv, rw.x, bw0); bw1 = fmaf(lv, rw.y, bw1);
        bw2 = fmaf(lv, rw.z, bw2); bw3 = fmaf(lv, rw.w, bw3);
    }
    float fw0 = g_fwd[(b*RR+0)*NN+tid], fw1 = g_fwd[(b*RR+1)*NN+tid];
    float fw2 = g_fwd[(b*RR+2)*NN+tid], fw3 = g_fwd[(b*RR+3)*NN+tid];

    // read content sim: warp-per-row over NEW M
    for (int p2=0;p2<32;p2++){
        int n = wi*32 + p2;
        const float* Mr = g_M + (b*NN + n)*WD;
        float m0 = Mr[l], m1 = Mr[l+32];
        float4 a = rk4[l], c = rk4[l+32];
        float ns = m0*m0 + m1*m1;
        float d0 = m0*a.x + m1*c.x;
        float d1 = m0*a.y + m1*c.y;
        float d2 = m0*a.z + m1*c.z;
        float d3 = m0*a.w + m1*c.w;
        ns=wredsum(ns); d0=wredsum(d0); d1=wredsum(d1); d2=wredsum(d2); d3=wredsum(d3);
        if (l==0){
            float inv = 1.f/(sqrtf(ns)+FEPS);
            simL[0][n]=d0*inv; simL[1][n]=d1*inv; simL[2][n]=d2*inv; simL[3][n]=d3*inv;
        }
    }
    __syncthreads();

    float rcv[4];
    #pragma unroll
    for (int r=0;r<4;r++){
        float logit = s_rbv[r] * simL[r][tid] / s_rknd[r];
        red[tid]=logit; __syncthreads();
        for (int s2=128;s2>0;s2>>=1){ if (tid<s2) red[tid]=fmaxf(red[tid],red[tid+s2]); __syncthreads(); }
        float mx = red[0]; __syncthreads();
        float e = expf(logit - mx);
        red[tid]=e; __syncthreads();
        for (int s2=128;s2>0;s2>>=1){ if (tid<s2) red[tid]+=red[tid+s2]; __syncthreads(); }
        rcv[r] = e/red[0]; __syncthreads();
    }

    float w0 = s_rm[0][0]*bw0 + s_rm[0][1]*rcv[0] + s_rm[0][2]*fw0;
    float w1 = s_rm[1][0]*bw1 + s_rm[1][1]*rcv[1] + s_rm[1][2]*fw1;
    float w2 = s_rm[2][0]*bw2 + s_rm[2][1]*rcv[2] + s_rm[2][2]*fw2;
    float w3 = s_rm[3][0]*bw3 + s_rm[3][1]*rcv[3] + s_rm[3][2]*fw3;
    g_rw[(b*RR+0)*NN+tid]=w0; g_rw[(b*RR+1)*NN+tid]=w1;
    g_rw[(b*RR+2)*NN+tid]=w2; g_rw[(b*RR+3)*NN+tid]=w3;
    rwn4[tid] = make_float4(w0,w1,w2,w3);
    __syncthreads();

    // rv[r,w] = sum_n M_new[n,w] * rw_new[r,n]
    int r = tid>>6, w = tid&63;
    float acc = 0.f;
    const float* Mb = g_M + b*NN*WD;
    #pragma unroll 4
    for (int n=0;n<NN;n++){
        float rv = (reinterpret_cast<const float*>(&rwn4[n]))[r];
        acc = fmaf(Mb[n*WD + w], rv, acc);
    }
    g_rv[b*(RR*WD) + tid] = acc;
}

// ---------------- K6: out = pre_out + rv @ W_memout -----------------------------
// grid (4,16), 128 threads.
__global__ void k_out(const float* __restrict__ Wm, float* __restrict__ out, int t){
    int b = blockIdx.y, tid = threadIdx.x;
    __shared__ __align__(16) float s[RR*WD];
    if (tid < 128){ s[tid] = g_rv[b*(RR*WD)+tid]; s[tid+128] = g_rv[b*(RR*WD)+tid+128]; }
    __syncthreads();
    int j = blockIdx.x*128 + tid;
    const float* Wc = Wm + j;
    float a0 = g_po[b*OO + j], a1=0.f, a2=0.f, a3=0.f;
    #pragma unroll 4
    for (int k=0;k<RR*WD;k+=4){
        float4 sv = *reinterpret_cast<const float4*>(&s[k]);
        a0 = fmaf(sv.x, Wc[(k+0)*OO], a0);
        a1 = fmaf(sv.y, Wc[(k+1)*OO], a1);
        a2 = fmaf(sv.z, Wc[(k+2)*OO], a2);
        a3 = fmaf(sv.w, Wc[(k+3)*OO], a3);
    }
    out[(t*BB + b)*OO + j] = (a0+a1)+(a2+a3);
}

// ---------------- launch --------------------------------------------------------
extern "C" void kernel_launch(void* const* d_in, const int* in_sizes, int n_in,
                              void* d_out, int out_size){
    const float* x  = (const float*)d_in[0];   // (64,16,512)
    const float* Wh = (const float*)d_in[1];   // (768,512)
    const float* bh = (const float*)d_in[2];   // (512,)
    const float* Wi = (const float*)d_in[3];   // (512,471)
    const float* Wo = (const float*)d_in[4];   // (512,512)
    const float* Wm = (const float*)d_in[5];   // (256,512)
    float* out = (float*)d_out;                // (64,16,512)

    k_init<<<256,256>>>();
    for (int t=0;t<TT;t++){
        int par = t & 1;
        k_hidden <<<dim3(4,BB),128>>>(x, Wh, bh, t);
        k_proj   <<<dim3(8,BB),128>>>(Wo, Wi);
        k_control<<<BB,256>>>(par);
        k_meml   <<<dim3(32,BB),256>>>(par);
        k_read   <<<BB,256>>>();
        k_out    <<<dim3(4,BB),128>>>(Wm, out, t);
    }
}

// round 7
// speedup vs baseline: 1.3879x; 1.3879x over previous
#include <cuda_runtime.h>
#include <math.h>

#define TT  64
#define BB  16
#define II  512
#define HH  512
#define OO  512
#define NN  256
#define WD  64
#define RR  4
#define NIN 768
#define IFW 471
#define FEPS 1e-6f

// ---------------- persistent state -------------
__device__ float g_M [BB*NN*WD];
__device__ float g_u [BB*NN];
__device__ float g_p [2][BB*NN];
__device__ float g_ww[BB*NN];
__device__ float g_L [BB*NN*NN];
__device__ float g_rw[BB*RR*NN];
__device__ float g_rv[BB*RR*WD];
__device__ float g_h  [BB*HH];
__device__ float g_po [BB*OO];
__device__ float g_if [BB*IFW];
__device__ float g_fwd[BB*RR*NN];

__device__ __forceinline__ float sigm(float x){ return 1.f/(1.f+expf(-x)); }
__device__ __forceinline__ float oneplus(float x){ return 1.f + (x > 20.f ? x : log1pf(expf(x))); }

// ---------------- init ------------------
__global__ void k_init(){
    int i0 = blockIdx.x*blockDim.x + threadIdx.x;
    int st = gridDim.x*blockDim.x;
    for (int i=i0;i<BB*NN*NN;i+=st) g_L[i]=0.f;
    for (int i=i0;i<BB*NN*WD;i+=st) g_M[i]=1e-6f;
    for (int i=i0;i<BB*NN;i+=st){ g_u[i]=0.f; g_p[0][i]=0.f; g_p[1][i]=0.f; g_ww[i]=0.f; }
    for (int i=i0;i<BB*RR*NN;i+=st) g_rw[i]=0.f;
    for (int i=i0;i<BB*RR*WD;i+=st) g_rv[i]=0.f;
}

// ---------------- K1: h = relu([x,rv]@W_hid + b), batch-shared -----------------
// grid 16 CTAs x 256 thr. CTA = 32 columns for ALL 16 batches.
// thread = (kg, jl): kg in [0,8) k-group, jl in [0,32) column.
__global__ __launch_bounds__(256) void k_hidden(const float* __restrict__ x,
        const float* __restrict__ Wh, const float* __restrict__ bh, int t){
    __shared__ __align__(16) float s[BB*NIN];   // [b][k], 48KB; reused for partials
    int tid = threadIdx.x;
    #pragma unroll
    for (int b=0;b<BB;b++)
        for (int k=tid;k<NIN;k+=256)
            s[b*NIN+k] = (k<II) ? x[(t*BB+b)*II + k] : g_rv[b*(RR*WD) + (k-II)];
    __syncthreads();

    int kg = tid>>5, jl = tid&31;
    int j = blockIdx.x*32 + jl;
    const float* Wc = Wh + j;
    float acc[BB];
    #pragma unroll
    for (int b=0;b<BB;b++) acc[b]=0.f;
    int k0 = kg*(NIN/8);                         // 96 k per group
    #pragma unroll 2
    for (int kk=0; kk<NIN/8; kk+=4){
        int k = k0+kk;
        float w0 = Wc[(k+0)*HH], w1 = Wc[(k+1)*HH], w2 = Wc[(k+2)*HH], w3 = Wc[(k+3)*HH];
        #pragma unroll
        for (int b=0;b<BB;b++){
            float4 v = *reinterpret_cast<const float4*>(&s[b*NIN+k]);
            acc[b] = fmaf(v.x,w0, fmaf(v.y,w1, fmaf(v.z,w2, fmaf(v.w,w3, acc[b]))));
        }
    }
    __syncthreads();
    #pragma unroll
    for (int b=0;b<BB;b++) s[kg*512 + b*32 + jl] = acc[b];
    __syncthreads();
    for (int p=tid;p<512;p+=256){
        int b = p>>5, jj = p&31;
        int jo = blockIdx.x*32 + jj;
        float sum = bh[jo];
        #pragma unroll
        for (int g=0;g<8;g++) sum += s[g*512 + b*32 + jj];
        g_h[b*HH + jo] = fmaxf(sum, 0.f);
    }
}

// ---------------- K2: pre_out = h@W_out ; iface = h@W_iface (batch-shared) -----
// grid 31 CTAs x 256 thr; CTAs 0..15 -> W_out cols, 16..30 -> W_iface cols.
__global__ __launch_bounds__(256) void k_proj(const float* __restrict__ Wo,
                                              const float* __restrict__ Wi){
    __shared__ __align__(16) float s[BB*HH];    // 32KB, reused for partials
    int tid = threadIdx.x;
    for (int i=tid;i<BB*HH;i+=256) s[i] = g_h[i];
    __syncthreads();

    int kg = tid>>5, jl = tid&31;
    int j = blockIdx.x*32 + jl;
    const float* Wc; int stride;
    if (j < OO){ Wc = Wo + j; stride = OO; }
    else { int jj = j - OO; if (jj > IFW-1) jj = IFW-1; Wc = Wi + jj; stride = IFW; }
    float acc[BB];
    #pragma unroll
    for (int b=0;b<BB;b++) acc[b]=0.f;
    int k0 = kg*(HH/8);                          // 64 k per group
    #pragma unroll 2
    for (int kk=0; kk<HH/8; kk+=4){
        int k = k0+kk;
        float w0 = Wc[(k+0)*stride], w1 = Wc[(k+1)*stride];
        float w2 = Wc[(k+2)*stride], w3 = Wc[(k+3)*stride];
        #pragma unroll
        for (int b=0;b<BB;b++){
            float4 v = *reinterpret_cast<const float4*>(&s[b*HH+k]);
            acc[b] = fmaf(v.x,w0, fmaf(v.y,w1, fmaf(v.z,w2, fmaf(v.w,w3, acc[b]))));
        }
    }
    __syncthreads();
    #pragma unroll
    for (int b=0;b<BB;b++) s[kg*512 + b*32 + jl] = acc[b];
    __syncthreads();
    for (int p=tid;p<512;p+=256){
        int b = p>>5, jj = p&31;
        int jo = blockIdx.x*32 + jj;
        float sum = 0.f;
        #pragma unroll
        for (int g=0;g<8;g++) sum += s[g*512 + b*32 + jj];
        if (jo < OO) g_po[b*OO + jo] = sum;
        else if (jo - OO < IFW) g_if[b*IFW + (jo-OO)] = sum;
    }
}

// ---------------- K3: gates, usage, rank-sort alloc, write weights, precedence --
// grid 16 x 256. Dynamic smem: M^T tile padded (256 x 65 floats).
__global__ __launch_bounds__(256) void k_control(int par){
    extern __shared__ float smT[];              // 256*65
    __shared__ float sk[256], ss[256], sc[256], wk_s[64];
    __shared__ float red8[8];
    int b = blockIdx.x, tid = threadIdx.x;
    int wi = tid>>5, l = tid&31;
    const float* ifc = g_if + b*IFW;

    for (int i=tid;i<NN*WD;i+=256){
        int n=i>>6, w=i&63;
        smT[n*65+w] = g_M[(b*NN+n)*WD + w];
    }
    if (tid<64) wk_s[tid] = ifc[260+tid];

    float fg0 = sigm(ifc[453]), fg1 = sigm(ifc[454]);
    float fg2 = sigm(ifc[455]), fg3 = sigm(ifc[456]);
    float u   = g_u [b*NN + tid];
    float wwo = g_ww[b*NN + tid];
    float ret = (1.f - fg0*g_rw[(b*RR+0)*NN+tid])
              * (1.f - fg1*g_rw[(b*RR+1)*NN+tid])
              * (1.f - fg2*g_rw[(b*RR+2)*NN+tid])
              * (1.f - fg3*g_rw[(b*RR+3)*NN+tid]);
    float un = (u + wwo - u*wwo) * ret;
    g_u[b*NN + tid] = un;
    sk[tid] = un;
    __syncthreads();                                           // A

    // rank = stable-argsort position of this slot
    int rank = 0;
    #pragma unroll 4
    for (int jx=0;jx<256;jx++){
        float kj = sk[jx];
        rank += (int)((kj < un) || (kj == un && jx < tid));
    }
    ss[rank] = un;
    __syncthreads();                                           // B

    // exclusive cumprod over sorted usage via warp product scan
    float v = ss[tid];
    float pscan = v;
    #pragma unroll
    for (int o=1;o<32;o<<=1){
        float t2 = __shfl_up_sync(0xffffffffu, pscan, o);
        if (l >= o) pscan *= t2;
    }
    if (l==31) red8[wi] = pscan;
    __syncthreads();                                           // C
    float wpre = 1.f;
    for (int g=0; g<wi; g++) wpre *= red8[g];
    float incl = pscan * wpre;
    float prev = __shfl_up_sync(0xffffffffu, incl, 1);
    float excl = (l==0) ? wpre : prev;
    sc[tid] = excl;
    __syncthreads();                                           // D
    float a = (1.f - un) * sc[rank];

    // content write weight: per-thread row dot from padded M^T
    float ns=0.f, dt=0.f, kk2=0.f;
    #pragma unroll 8
    for (int w=0;w<64;w++){
        float m = smT[tid*65+w];
        float k = wk_s[w];
        ns = fmaf(m,m,ns); dt = fmaf(m,k,dt); kk2 = fmaf(k,k,kk2);
    }
    float wb = oneplus(ifc[324]);
    float logit = wb * (dt / (sqrtf(ns)+FEPS)) / (sqrtf(kk2)+FEPS);

    // softmax (butterfly + 8 partials)
    float mx = logit;
    #pragma unroll
    for (int o=16;o;o>>=1) mx = fmaxf(mx, __shfl_xor_sync(0xffffffffu, mx, o));
    if (l==0) red8[wi] = mx;
    __syncthreads();                                           // E
    float gmx = red8[0];
    #pragma unroll
    for (int g=1;g<8;g++) gmx = fmaxf(gmx, red8[g]);
    __syncthreads();                                           // F
    float e = expf(logit - gmx);
    float sm = e;
    #pragma unroll
    for (int o=16;o;o>>=1) sm += __shfl_xor_sync(0xffffffffu, sm, o);
    if (l==0) red8[wi] = sm;
    __syncthreads();                                           // G
    float tot = 0.f;
    #pragma unroll
    for (int g=0;g<8;g++) tot += red8[g];
    float cw = e / tot;

    float ag = sigm(ifc[457]), wg = sigm(ifc[458]);
    float wwn = wg * (ag*a + (1.f-ag)*cw);
    g_ww[b*NN + tid] = wwn;

    __syncthreads();                                           // H (red8 reuse)
    float sw = wwn;
    #pragma unroll
    for (int o=16;o;o>>=1) sw += __shfl_xor_sync(0xffffffffu, sw, o);
    if (l==0) red8[wi] = sw;
    __syncthreads();                                           // I
    float S = 0.f;
    #pragma unroll
    for (int g=0;g<8;g++) S += red8[g];
    float po = g_p[par][b*NN + tid];
    g_p[par^1][b*NN + tid] = (1.f - S)*po + wwn;
}

// ---------------- K4: M update + L update fused with fwd ------------------------
__global__ __launch_bounds__(256) void k_meml(int par){
    int b = blockIdx.y, n0 = blockIdx.x*8;
    int tid = threadIdx.x, wi = tid>>5, l = tid&31;
    const float* ifc = g_if + b*IFW;

    #pragma unroll
    for (int q=0;q<2;q++){
        int idx = tid + q*256;
        int n = n0 + (idx>>6), w = idx & 63;
        float wwn = g_ww[b*NN + n];
        float ev  = sigm(ifc[325 + w]);
        float wv  = ifc[389 + w];
        float m   = g_M[(b*NN + n)*WD + w];
        g_M[(b*NN + n)*WD + w] = m*(1.f - wwn*ev) + wwn*wv;
    }

    int n = n0 + wi;
    float wwn = g_ww[b*NN + n];
    float* Lr = g_L + (b*NN + n)*NN;
    const float* pw  = g_p[par] + b*NN;
    const float* wwp = g_ww + b*NN;
    const float* rwp = g_rw + b*RR*NN;
    float f0=0.f,f1=0.f,f2=0.f,f3=0.f;
    #pragma unroll
    for (int k=0;k<8;k++){
        int m = l + k*32;
        float lo = Lr[m];
        float ln = (1.f - wwn - wwp[m])*lo + wwn*pw[m];
        if (m == n) ln = 0.f;
        Lr[m] = ln;
        f0 = fmaf(ln, rwp[0*NN+m], f0);
        f1 = fmaf(ln, rwp[1*NN+m], f1);
        f2 = fmaf(ln, rwp[2*NN+m], f2);
        f3 = fmaf(ln, rwp[3*NN+m], f3);
    }
    #pragma unroll
    for (int o=16;o;o>>=1){
        f0 += __shfl_xor_sync(0xffffffffu, f0, o);
        f1 += __shfl_xor_sync(0xffffffffu, f1, o);
        f2 += __shfl_xor_sync(0xffffffffu, f2, o);
        f3 += __shfl_xor_sync(0xffffffffu, f3, o);
    }
    if (l==0){
        g_fwd[(b*RR+0)*NN+n]=f0; g_fwd[(b*RR+1)*NN+n]=f1;
        g_fwd[(b*RR+2)*NN+n]=f2; g_fwd[(b*RR+3)*NN+n]=f3;
    }
}

// ---------------- K5: bwd, read softmax, rw_new, rv_new -------------------------
__global__ __launch_bounds__(256) void k_read(){
    extern __shared__ float smT[];              // 256*65 (NEW M)
    __shared__ float4 rw4[256], rwn4[256], rk4[64];
    __shared__ float4 red4[8];
    int b = blockIdx.x, tid = threadIdx.x, wi = tid>>5, l = tid&31;
    const float* ifc = g_if + b*IFW;
    const float* rwp = g_rw + b*RR*NN;

    for (int i=tid;i<NN*WD;i+=256){
        int n=i>>6, w=i&63;
        smT[n*65+w] = g_M[(b*NN+n)*WD + w];
    }
    rw4[tid] = make_float4(rwp[tid], rwp[NN+tid], rwp[2*NN+tid], rwp[3*NN+tid]);
    if (tid < 64) rk4[tid] = make_float4(ifc[tid], ifc[64+tid], ifc[128+tid], ifc[192+tid]);
    __syncthreads();

    // bwd: coalesced column scan of L_new, MLP via unroll 8
    float bw0=0.f,bw1=0.f,bw2=0.f,bw3=0.f;
    const float* Lb = g_L + b*NN*NN;
    #pragma unroll 8
    for (int m=0;m<NN;m++){
        float lv = Lb[m*NN + tid];
        float4 rw = rw4[m];
        bw0 = fmaf(lv, rw.x, bw0); bw1 = fmaf(lv, rw.y, bw1);
        bw2 = fmaf(lv, rw.z, bw2); bw3 = fmaf(lv, rw.w, bw3);
    }

    // read-content sims: per-thread row dot from padded M^T
    float ns=0.f,d0=0.f,d1=0.f,d2=0.f,d3=0.f,n0=0.f,n1=0.f,n2=0.f,n3=0.f;
    #pragma unroll 8
    for (int w=0;w<64;w++){
        float m = smT[tid*65+w];
        float4 k = rk4[w];
        ns = fmaf(m,m,ns);
        d0 = fmaf(m,k.x,d0); d1 = fmaf(m,k.y,d1);
        d2 = fmaf(m,k.z,d2); d3 = fmaf(m,k.w,d3);
        n0 = fmaf(k.x,k.x,n0); n1 = fmaf(k.y,k.y,n1);
        n2 = fmaf(k.z,k.z,n2); n3 = fmaf(k.w,k.w,n3);
    }
    float inm = 1.f/(sqrtf(ns)+FEPS);
    float lg0 = oneplus(ifc[256]) * d0*inm / (sqrtf(n0)+FEPS);
    float lg1 = oneplus(ifc[257]) * d1*inm / (sqrtf(n1)+FEPS);
    float lg2 = oneplus(ifc[258]) * d2*inm / (sqrtf(n2)+FEPS);
    float lg3 = oneplus(ifc[259]) * d3*inm / (sqrtf(n3)+FEPS);

    // 4-way interleaved softmax over slots
    float m0=lg0,m1=lg1,m2=lg2,m3=lg3;
    #pragma unroll
    for (int o=16;o;o>>=1){
        m0=fmaxf(m0,__shfl_xor_sync(0xffffffffu,m0,o));
        m1=fmaxf(m1,__shfl_xor_sync(0xffffffffu,m1,o));
        m2=fmaxf(m2,__shfl_xor_sync(0xffffffffu,m2,o));
        m3=fmaxf(m3,__shfl_xor_sync(0xffffffffu,m3,o));
    }
    if (l==0) red4[wi] = make_float4(m0,m1,m2,m3);
    __syncthreads();
    float4 mxv = red4[0];
    #pragma unroll
    for (int g=1;g<8;g++){
        float4 r = red4[g];
        mxv.x=fmaxf(mxv.x,r.x); mxv.y=fmaxf(mxv.y,r.y);
        mxv.z=fmaxf(mxv.z,r.z); mxv.w=fmaxf(mxv.w,r.w);
    }
    __syncthreads();
    float e0=expf(lg0-mxv.x), e1=expf(lg1-mxv.y), e2=expf(lg2-mxv.z), e3=expf(lg3-mxv.w);
    float s0=e0,s1=e1,s2=e2,s3=e3;
    #pragma unroll
    for (int o=16;o;o>>=1){
        s0+=__shfl_xor_sync(0xffffffffu,s0,o);
        s1+=__shfl_xor_sync(0xffffffffu,s1,o);
        s2+=__shfl_xor_sync(0xffffffffu,s2,o);
        s3+=__shfl_xor_sync(0xffffffffu,s3,o);
    }
    if (l==0) red4[wi] = make_float4(s0,s1,s2,s3);
    __syncthreads();
    float4 tv = make_float4(0,0,0,0);
    #pragma unroll
    for (int g=0;g<8;g++){
        float4 r = red4[g];
        tv.x+=r.x; tv.y+=r.y; tv.z+=r.z; tv.w+=r.w;
    }
    float rc0=e0/tv.x, rc1=e1/tv.y, rc2=e2/tv.z, rc3=e3/tv.w;

    // read mode gates (per-thread redundant, cheap)
    float rm[4][3];
    #pragma unroll
    for (int r=0;r<4;r++){
        float v0=ifc[459+3*r], v1=ifc[460+3*r], v2=ifc[461+3*r];
        float mxg = fmaxf(v0, fmaxf(v1, v2));
        float a0=expf(v0-mxg), a1=expf(v1-mxg), a2=expf(v2-mxg);
        float inv = 1.f/(a0+a1+a2);
        rm[r][0]=a0*inv; rm[r][1]=a1*inv; rm[r][2]=a2*inv;
    }
    float fw0 = g_fwd[(b*RR+0)*NN+tid], fw1 = g_fwd[(b*RR+1)*NN+tid];
    float fw2 = g_fwd[(b*RR+2)*NN+tid], fw3 = g_fwd[(b*RR+3)*NN+tid];

    float w0 = rm[0][0]*bw0 + rm[0][1]*rc0 + rm[0][2]*fw0;
    float w1 = rm[1][0]*bw1 + rm[1][1]*rc1 + rm[1][2]*fw1;
    float w2 = rm[2][0]*bw2 + rm[2][1]*rc2 + rm[2][2]*fw2;
    float w3 = rm[3][0]*bw3 + rm[3][1]*rc3 + rm[3][2]*fw3;
    g_rw[(b*RR+0)*NN+tid]=w0; g_rw[(b*RR+1)*NN+tid]=w1;
    g_rw[(b*RR+2)*NN+tid]=w2; g_rw[(b*RR+3)*NN+tid]=w3;
    rwn4[tid] = make_float4(w0,w1,w2,w3);
    __syncthreads();

    // rv[r,w] = sum_n M_new[n,w] * rw_new[r,n]  (M from smem)
    int r = tid>>6, w = tid&63;
    float acc = 0.f;
    #pragma unroll 8
    for (int n=0;n<NN;n++){
        float rv = (reinterpret_cast<const float*>(&rwn4[n]))[r];
        acc = fmaf(smT[n*65 + w], rv, acc);
    }
    g_rv[b*(RR*WD) + tid] = acc;
}

// ---------------- K6: out = pre_out + rv @ W_memout (batch-shared) --------------
__global__ __launch_bounds__(256) void k_out(const float* __restrict__ Wm,
                                             float* __restrict__ out, int t){
    __shared__ __align__(16) float s[BB*RR*WD];  // 16KB, reused for partials
    int tid = threadIdx.x;
    for (int i=tid;i<BB*RR*WD;i+=256) s[i] = g_rv[i];
    __syncthreads();

    int kg = tid>>5, jl = tid&31;
    int j = blockIdx.x*32 + jl;
    const float* Wc = Wm + j;
    float acc[BB];
    #pragma unroll
    for (int b=0;b<BB;b++) acc[b]=0.f;
    int k0 = kg*32;                              // 256/8
    #pragma unroll 2
    for (int kk=0; kk<32; kk+=4){
        int k = k0+kk;
        float w0 = Wc[(k+0)*OO], w1 = Wc[(k+1)*OO], w2 = Wc[(k+2)*OO], w3 = Wc[(k+3)*OO];
        #pragma unroll
        for (int b=0;b<BB;b++){
            float4 v = *reinterpret_cast<const float4*>(&s[b*(RR*WD)+k]);
            acc[b] = fmaf(v.x,w0, fmaf(v.y,w1, fmaf(v.z,w2, fmaf(v.w,w3, acc[b]))));
        }
    }
    __syncthreads();
    #pragma unroll
    for (int b=0;b<BB;b++) s[kg*512 + b*32 + jl] = acc[b];
    __syncthreads();
    for (int p=tid;p<512;p+=256){
        int b = p>>5, jj = p&31;
        int jo = blockIdx.x*32 + jj;
        float sum = g_po[b*OO + jo];
        #pragma unroll
        for (int g=0;g<8;g++) sum += s[g*512 + b*32 + jj];
        out[(t*BB + b)*OO + jo] = sum;
    }
}

// ---------------- launch --------------------------------------------------------
extern "C" void kernel_launch(void* const* d_in, const int* in_sizes, int n_in,
                              void* d_out, int out_size){
    const float* x  = (const float*)d_in[0];
    const float* Wh = (const float*)d_in[1];
    const float* bh = (const float*)d_in[2];
    const float* Wi = (const float*)d_in[3];
    const float* Wo = (const float*)d_in[4];
    const float* Wm = (const float*)d_in[5];
    float* out = (float*)d_out;

    const int dynS = NN*65*sizeof(float);   // 66560 B
    cudaFuncSetAttribute(k_control, cudaFuncAttributeMaxDynamicSharedMemorySize, dynS);
    cudaFuncSetAttribute(k_read,    cudaFuncAttributeMaxDynamicSharedMemorySize, dynS);

    k_init<<<256,256>>>();
    for (int t=0;t<TT;t++){
        int par = t & 1;
        k_hidden <<<16,256>>>(x, Wh, bh, t);
        k_proj   <<<31,256>>>(Wo, Wi);
        k_control<<<BB,256,dynS>>>(par);
        k_meml   <<<dim3(32,BB),256>>>(par);
        k_read   <<<BB,256,dynS>>>();
        k_out    <<<16,256>>>(Wm, out, t);
    }
}

// round 8
// speedup vs baseline: 1.6590x; 1.1953x over previous
#include <cuda_runtime.h>
#include <math.h>

#define TT  64
#define BB  16
#define II  512
#define HH  512
#define OO  512
#define NN  256
#define WD  64
#define RR  4
#define NIN 768
#define IFW 471
#define FEPS 1e-6f

// ---------------- persistent state -------------
__device__ float g_M [BB*NN*WD];
__device__ float g_u [BB*NN];
__device__ float g_p [2][BB*NN];
__device__ float g_ww[BB*NN];
__device__ float g_L [BB*NN*NN];
__device__ float g_rw[BB*RR*NN];
__device__ float g_rv[BB*RR*WD];
__device__ float g_h  [BB*HH];
__device__ float g_po [BB*OO];
__device__ float g_if [BB*IFW];
__device__ float g_fwd[BB*RR*NN];
__device__ float g_simw[BB*NN];        // write-content cosine (pre beta)
__device__ float g_rsim[BB*RR*NN];     // read-content dot / (|m|+eps)

__device__ __forceinline__ float sigm(float x){ return 1.f/(1.f+expf(-x)); }
__device__ __forceinline__ float oneplus(float x){ return 1.f + (x > 20.f ? x : log1pf(expf(x))); }

// ---------------- init ------------------
__global__ void k_init(){
    int i0 = blockIdx.x*blockDim.x + threadIdx.x;
    int st = gridDim.x*blockDim.x;
    for (int i=i0;i<BB*NN*NN;i+=st) g_L[i]=0.f;
    for (int i=i0;i<BB*NN*WD;i+=st) g_M[i]=1e-6f;
    for (int i=i0;i<BB*NN;i+=st){ g_u[i]=0.f; g_p[0][i]=0.f; g_p[1][i]=0.f; g_ww[i]=0.f; }
    for (int i=i0;i<BB*RR*NN;i+=st) g_rw[i]=0.f;
    for (int i=i0;i<BB*RR*WD;i+=st) g_rv[i]=0.f;
}

// ---------------- K1: out(t-1) = po + rv@Wm  AND  h = relu([x,rv]@W_hid + b) ----
// grid 32 CTAs x 256 thr; 16-column tile per CTA for all 16 batches.
__global__ __launch_bounds__(256) void k_hidout(const float* __restrict__ x,
        const float* __restrict__ Wh, const float* __restrict__ bh,
        const float* __restrict__ Wm, float* __restrict__ out, int t){
    extern __shared__ __align__(16) float s[];   // [0, BB*NIN) inputs; then 4096 partials
    float* sp = s + BB*NIN;
    int tid = threadIdx.x;
    #pragma unroll
    for (int b=0;b<BB;b++)
        for (int k=tid;k<NIN;k+=256)
            s[b*NIN+k] = (k<II) ? x[(t*BB+b)*II + k] : g_rv[b*(RR*WD) + (k-II)];
    __syncthreads();

    int kg = tid>>4, jl = tid&15;
    int j = blockIdx.x*16 + jl;

    // ---- out for step t-1 (rv(t-1) is already staged in s) ----
    if (t > 0){
        const float* Wc = Wm + j;
        float acc[BB];
        #pragma unroll
        for (int b=0;b<BB;b++) acc[b]=0.f;
        int k0 = kg*16;
        #pragma unroll
        for (int kk=0; kk<16; kk+=4){
            int k = k0+kk;
            float w0 = Wc[(k+0)*OO], w1 = Wc[(k+1)*OO], w2 = Wc[(k+2)*OO], w3 = Wc[(k+3)*OO];
            #pragma unroll
            for (int b=0;b<BB;b++){
                float4 v = *reinterpret_cast<const float4*>(&s[b*NIN + II + k]);
                acc[b] = fmaf(v.x,w0, fmaf(v.y,w1, fmaf(v.z,w2, fmaf(v.w,w3, acc[b]))));
            }
        }
        __syncthreads();
        #pragma unroll
        for (int b=0;b<BB;b++) sp[kg*256 + b*16 + jl] = acc[b];
        __syncthreads();
        for (int p=tid;p<256;p+=256){
            int b = p>>4, jj = p&15;
            int jo = blockIdx.x*16 + jj;
            float sum = g_po[b*OO + jo];
            #pragma unroll
            for (int g=0;g<16;g++) sum += sp[g*256 + p];
            out[((t-1)*BB + b)*OO + jo] = sum;
        }
        __syncthreads();
    }

    // ---- hidden ----
    const float* Wc = Wh + j;
    float acc[BB];
    #pragma unroll
    for (int b=0;b<BB;b++) acc[b]=0.f;
    int k0 = kg*48;
    #pragma unroll 3
    for (int kk=0; kk<48; kk+=4){
        int k = k0+kk;
        float w0 = Wc[(k+0)*HH], w1 = Wc[(k+1)*HH], w2 = Wc[(k+2)*HH], w3 = Wc[(k+3)*HH];
        #pragma unroll
        for (int b=0;b<BB;b++){
            float4 v = *reinterpret_cast<const float4*>(&s[b*NIN+k]);
            acc[b] = fmaf(v.x,w0, fmaf(v.y,w1, fmaf(v.z,w2, fmaf(v.w,w3, acc[b]))));
        }
    }
    __syncthreads();
    #pragma unroll
    for (int b=0;b<BB;b++) sp[kg*256 + b*16 + jl] = acc[b];
    __syncthreads();
    for (int p=tid;p<256;p+=256){
        int b = p>>4, jj = p&15;
        int jo = blockIdx.x*16 + jj;
        float sum = bh[jo];
        #pragma unroll
        for (int g=0;g<16;g++) sum += sp[g*256 + p];
        g_h[b*HH + jo] = fmaxf(sum, 0.f);
    }
}

// ---------------- K2: pre_out = h@W_out ; iface = h@W_iface ---------------------
// grid 62 CTAs x 256 thr; 16-column tiles; CTAs 0..31 -> W_out, 32..61 -> W_iface.
__global__ __launch_bounds__(256) void k_proj(const float* __restrict__ Wo,
                                              const float* __restrict__ Wi){
    extern __shared__ __align__(16) float s[];   // BB*HH + 4096
    float* sp = s + BB*HH;
    int tid = threadIdx.x;
    for (int i=tid;i<BB*HH;i+=256) s[i] = g_h[i];
    __syncthreads();

    int kg = tid>>4, jl = tid&15;
    int j = blockIdx.x*16 + jl;
    const float* Wc; int stride;
    if (j < OO){ Wc = Wo + j; stride = OO; }
    else { int jj = j - OO; if (jj > IFW-1) jj = IFW-1; Wc = Wi + jj; stride = IFW; }
    float acc[BB];
    #pragma unroll
    for (int b=0;b<BB;b++) acc[b]=0.f;
    int k0 = kg*32;
    #pragma unroll 2
    for (int kk=0; kk<32; kk+=4){
        int k = k0+kk;
        float w0 = Wc[(k+0)*stride], w1 = Wc[(k+1)*stride];
        float w2 = Wc[(k+2)*stride], w3 = Wc[(k+3)*stride];
        #pragma unroll
        for (int b=0;b<BB;b++){
            float4 v = *reinterpret_cast<const float4*>(&s[b*HH+k]);
            acc[b] = fmaf(v.x,w0, fmaf(v.y,w1, fmaf(v.z,w2, fmaf(v.w,w3, acc[b]))));
        }
    }
    __syncthreads();
    #pragma unroll
    for (int b=0;b<BB;b++) sp[kg*256 + b*16 + jl] = acc[b];
    __syncthreads();
    for (int p=tid;p<256;p+=256){
        int b = p>>4, jj = p&15;
        int jo = blockIdx.x*16 + jj;
        float sum = 0.f;
        #pragma unroll
        for (int g=0;g<16;g++) sum += sp[g*256 + p];
        if (jo < OO) g_po[b*OO + jo] = sum;
        else if (jo - OO < IFW) g_if[b*IFW + (jo-OO)] = sum;
    }
}

// ---------------- K2b: write-content cosine (wide, 128 CTAs) --------------------
// grid (8,16) x 256; CTA handles 32 slots, warp-per-4-rows over OLD M.
__global__ __launch_bounds__(256) void k_wsim(){
    int b = blockIdx.y, c = blockIdx.x;
    int tid = threadIdx.x, wi = tid>>5, l = tid&31;
    __shared__ float wk_s[64];
    __shared__ float s_den;
    const float* ifc = g_if + b*IFW;
    if (tid < 64) wk_s[tid] = ifc[260+tid];
    __syncthreads();
    if (tid < 32){
        float w0 = wk_s[l], w1 = wk_s[l+32];
        float ss = w0*w0 + w1*w1;
        #pragma unroll
        for (int o=16;o;o>>=1) ss += __shfl_xor_sync(0xffffffffu, ss, o);
        if (l==0) s_den = sqrtf(ss) + FEPS;
    }
    __syncthreads();
    float k0 = wk_s[l], k1 = wk_s[l+32];
    float den_k = s_den;
    #pragma unroll
    for (int p2=0;p2<4;p2++){
        int n = c*32 + wi*4 + p2;
        const float* Mr = g_M + (b*NN + n)*WD;
        float m0 = Mr[l], m1 = Mr[l+32];
        float ns = m0*m0 + m1*m1;
        float dt = m0*k0 + m1*k1;
        #pragma unroll
        for (int o=16;o;o>>=1){
            ns += __shfl_xor_sync(0xffffffffu, ns, o);
            dt += __shfl_xor_sync(0xffffffffu, dt, o);
        }
        if (l==0) g_simw[b*NN + n] = dt / ((sqrtf(ns)+FEPS) * den_k);
    }
}

// ---------------- K3: usage, rank-sort alloc, write weights, precedence ---------
__global__ __launch_bounds__(256) void k_control(int par){
    __shared__ float sk[256], ss[256], sc[256];
    __shared__ float red8[8];
    int b = blockIdx.x, tid = threadIdx.x;
    int wi = tid>>5, l = tid&31;
    const float* ifc = g_if + b*IFW;

    float fg0 = sigm(ifc[453]), fg1 = sigm(ifc[454]);
    float fg2 = sigm(ifc[455]), fg3 = sigm(ifc[456]);
    float u   = g_u [b*NN + tid];
    float wwo = g_ww[b*NN + tid];
    float ret = (1.f - fg0*g_rw[(b*RR+0)*NN+tid])
              * (1.f - fg1*g_rw[(b*RR+1)*NN+tid])
              * (1.f - fg2*g_rw[(b*RR+2)*NN+tid])
              * (1.f - fg3*g_rw[(b*RR+3)*NN+tid]);
    float un = (u + wwo - u*wwo) * ret;
    g_u[b*NN + tid] = un;
    sk[tid] = un;
    float simv = g_simw[b*NN + tid];
    __syncthreads();

    // rank = stable-argsort position
    int rank = 0;
    #pragma unroll 4
    for (int jx=0;jx<256;jx++){
        float kj = sk[jx];
        rank += (int)((kj < un) || (kj == un && jx < tid));
    }
    ss[rank] = un;
    __syncthreads();

    // exclusive product scan over sorted usage
    float pscan = ss[tid];
    #pragma unroll
    for (int o=1;o<32;o<<=1){
        float t2 = __shfl_up_sync(0xffffffffu, pscan, o);
        if (l >= o) pscan *= t2;
    }
    if (l==31) red8[wi] = pscan;
    __syncthreads();
    float wpre = 1.f;
    for (int g=0; g<wi; g++) wpre *= red8[g];
    float incl = pscan * wpre;
    float prev = __shfl_up_sync(0xffffffffu, incl, 1);
    float excl = (l==0) ? wpre : prev;
    sc[tid] = excl;
    __syncthreads();
    float a = (1.f - un) * sc[rank];

    // write-content softmax
    float wb = oneplus(ifc[324]);
    float logit = wb * simv;
    float mx = logit;
    #pragma unroll
    for (int o=16;o;o>>=1) mx = fmaxf(mx, __shfl_xor_sync(0xffffffffu, mx, o));
    if (l==0) red8[wi] = mx;
    __syncthreads();
    float gmx = red8[0];
    #pragma unroll
    for (int g=1;g<8;g++) gmx = fmaxf(gmx, red8[g]);
    __syncthreads();
    float e = expf(logit - gmx);
    float sm = e;
    #pragma unroll
    for (int o=16;o;o>>=1) sm += __shfl_xor_sync(0xffffffffu, sm, o);
    if (l==0) red8[wi] = sm;
    __syncthreads();
    float tot = 0.f;
    #pragma unroll
    for (int g=0;g<8;g++) tot += red8[g];
    float cw = e / tot;

    float ag = sigm(ifc[457]), wg = sigm(ifc[458]);
    float wwn = wg * (ag*a + (1.f-ag)*cw);
    g_ww[b*NN + tid] = wwn;

    __syncthreads();
    float sw = wwn;
    #pragma unroll
    for (int o=16;o;o>>=1) sw += __shfl_xor_sync(0xffffffffu, sw, o);
    if (l==0) red8[wi] = sw;
    __syncthreads();
    float S = 0.f;
    #pragma unroll
    for (int g=0;g<8;g++) S += red8[g];
    float po = g_p[par][b*NN + tid];
    g_p[par^1][b*NN + tid] = (1.f - S)*po + wwn;
}

// ---------------- K4: M update + read sims + L update + fwd (warp-per-row) ------
__global__ __launch_bounds__(256) void k_meml(int par){
    int b = blockIdx.y, n0 = blockIdx.x*8;
    int tid = threadIdx.x, wi = tid>>5, l = tid&31;
    const float* ifc = g_if + b*IFW;
    __shared__ float4 rk4[64];
    __shared__ float ev_s[64], wv_s[64];
    if (tid < 64){
        rk4[tid] = make_float4(ifc[tid], ifc[64+tid], ifc[128+tid], ifc[192+tid]);
        ev_s[tid] = sigm(ifc[325 + tid]);
        wv_s[tid] = ifc[389 + tid];
    }
    __syncthreads();

    int n = n0 + wi;
    float wwn = g_ww[b*NN + n];
    float* Mr = g_M + (b*NN + n)*WD;
    float m0 = Mr[l], m1 = Mr[l+32];
    m0 = m0*(1.f - wwn*ev_s[l   ]) + wwn*wv_s[l   ];
    m1 = m1*(1.f - wwn*ev_s[l+32]) + wwn*wv_s[l+32];
    Mr[l] = m0; Mr[l+32] = m1;

    // read-content dots over NEW M
    float4 a = rk4[l], c = rk4[l+32];
    float ns = m0*m0 + m1*m1;
    float d0 = m0*a.x + m1*c.x;
    float d1 = m0*a.y + m1*c.y;
    float d2 = m0*a.z + m1*c.z;
    float d3 = m0*a.w + m1*c.w;
    #pragma unroll
    for (int o=16;o;o>>=1){
        ns += __shfl_xor_sync(0xffffffffu, ns, o);
        d0 += __shfl_xor_sync(0xffffffffu, d0, o);
        d1 += __shfl_xor_sync(0xffffffffu, d1, o);
        d2 += __shfl_xor_sync(0xffffffffu, d2, o);
        d3 += __shfl_xor_sync(0xffffffffu, d3, o);
    }
    if (l==0){
        float inv = 1.f/(sqrtf(ns)+FEPS);
        g_rsim[(b*RR+0)*NN+n] = d0*inv;
        g_rsim[(b*RR+1)*NN+n] = d1*inv;
        g_rsim[(b*RR+2)*NN+n] = d2*inv;
        g_rsim[(b*RR+3)*NN+n] = d3*inv;
    }

    // link row update + fwd
    float* Lr = g_L + (b*NN + n)*NN;
    const float* pw  = g_p[par] + b*NN;
    const float* wwp = g_ww + b*NN;
    const float* rwp = g_rw + b*RR*NN;
    float f0=0.f,f1=0.f,f2=0.f,f3=0.f;
    #pragma unroll
    for (int k=0;k<8;k++){
        int m = l + k*32;
        float lo = Lr[m];
        float ln = (1.f - wwn - wwp[m])*lo + wwn*pw[m];
        if (m == n) ln = 0.f;
        Lr[m] = ln;
        f0 = fmaf(ln, rwp[0*NN+m], f0);
        f1 = fmaf(ln, rwp[1*NN+m], f1);
        f2 = fmaf(ln, rwp[2*NN+m], f2);
        f3 = fmaf(ln, rwp[3*NN+m], f3);
    }
    #pragma unroll
    for (int o=16;o;o>>=1){
        f0 += __shfl_xor_sync(0xffffffffu, f0, o);
        f1 += __shfl_xor_sync(0xffffffffu, f1, o);
        f2 += __shfl_xor_sync(0xffffffffu, f2, o);
        f3 += __shfl_xor_sync(0xffffffffu, f3, o);
    }
    if (l==0){
        g_fwd[(b*RR+0)*NN+n]=f0; g_fwd[(b*RR+1)*NN+n]=f1;
        g_fwd[(b*RR+2)*NN+n]=f2; g_fwd[(b*RR+3)*NN+n]=f3;
    }
}

// ---------------- K5: bwd, read softmax, rw_new, rv_new -------------------------
__global__ __launch_bounds__(256) void k_read(){
    __shared__ float4 rw4[256], rwn4[256];
    __shared__ float4 red4[8];
    __shared__ float s_knd[4];
    __shared__ float partial[8*256];
    int b = blockIdx.x, tid = threadIdx.x, wi = tid>>5, l = tid&31;
    const float* ifc = g_if + b*IFW;
    const float* rwp = g_rw + b*RR*NN;

    rw4[tid] = make_float4(rwp[tid], rwp[NN+tid], rwp[2*NN+tid], rwp[3*NN+tid]);
    if (wi < 4){   // head key norms
        float k0 = ifc[wi*64 + l], k1 = ifc[wi*64 + l + 32];
        float ss = k0*k0 + k1*k1;
        #pragma unroll
        for (int o=16;o;o>>=1) ss += __shfl_xor_sync(0xffffffffu, ss, o);
        if (l==0) s_knd[wi] = sqrtf(ss) + FEPS;
    }
    __syncthreads();

    // bwd: coalesced column scan of L_new
    float bw0=0.f,bw1=0.f,bw2=0.f,bw3=0.f;
    const float* Lb = g_L + b*NN*NN;
    #pragma unroll 8
    for (int m=0;m<NN;m++){
        float lv = Lb[m*NN + tid];
        float4 rw = rw4[m];
        bw0 = fmaf(lv, rw.x, bw0); bw1 = fmaf(lv, rw.y, bw1);
        bw2 = fmaf(lv, rw.z, bw2); bw3 = fmaf(lv, rw.w, bw3);
    }

    // read-content logits from precomputed sims
    float lg0 = oneplus(ifc[256]) * g_rsim[(b*RR+0)*NN+tid] / s_knd[0];
    float lg1 = oneplus(ifc[257]) * g_rsim[(b*RR+1)*NN+tid] / s_knd[1];
    float lg2 = oneplus(ifc[258]) * g_rsim[(b*RR+2)*NN+tid] / s_knd[2];
    float lg3 = oneplus(ifc[259]) * g_rsim[(b*RR+3)*NN+tid] / s_knd[3];

    float m0=lg0,m1=lg1,m2=lg2,m3=lg3;
    #pragma unroll
    for (int o=16;o;o>>=1){
        m0=fmaxf(m0,__shfl_xor_sync(0xffffffffu,m0,o));
        m1=fmaxf(m1,__shfl_xor_sync(0xffffffffu,m1,o));
        m2=fmaxf(m2,__shfl_xor_sync(0xffffffffu,m2,o));
        m3=fmaxf(m3,__shfl_xor_sync(0xffffffffu,m3,o));
    }
    if (l==0) red4[wi] = make_float4(m0,m1,m2,m3);
    __syncthreads();
    float4 mxv = red4[0];
    #pragma unroll
    for (int g=1;g<8;g++){
        float4 r = red4[g];
        mxv.x=fmaxf(mxv.x,r.x); mxv.y=fmaxf(mxv.y,r.y);
        mxv.z=fmaxf(mxv.z,r.z); mxv.w=fmaxf(mxv.w,r.w);
    }
    __syncthreads();
    float e0=expf(lg0-mxv.x), e1=expf(lg1-mxv.y), e2=expf(lg2-mxv.z), e3=expf(lg3-mxv.w);
    float s0=e0,s1=e1,s2=e2,s3=e3;
    #pragma unroll
    for (int o=16;o;o>>=1){
        s0+=__shfl_xor_sync(0xffffffffu,s0,o);
        s1+=__shfl_xor_sync(0xffffffffu,s1,o);
        s2+=__shfl_xor_sync(0xffffffffu,s2,o);
        s3+=__shfl_xor_sync(0xffffffffu,s3,o);
    }
    if (l==0) red4[wi] = make_float4(s0,s1,s2,s3);
    __syncthreads();
    float4 tv = make_float4(0,0,0,0);
    #pragma unroll
    for (int g=0;g<8;g++){
        float4 r = red4[g];
        tv.x+=r.x; tv.y+=r.y; tv.z+=r.z; tv.w+=r.w;
    }
    float rc0=e0/tv.x, rc1=e1/tv.y, rc2=e2/tv.z, rc3=e3/tv.w;

    // read-mode gates (redundant per-thread, cheap)
    float rm[4][3];
    #pragma unroll
    for (int r=0;r<4;r++){
        float v0=ifc[459+3*r], v1=ifc[460+3*r], v2=ifc[461+3*r];
        float mxg = fmaxf(v0, fmaxf(v1, v2));
        float a0=expf(v0-mxg), a1=expf(v1-mxg), a2=expf(v2-mxg);
        float inv = 1.f/(a0+a1+a2);
        rm[r][0]=a0*inv; rm[r][1]=a1*inv; rm[r][2]=a2*inv;
    }
    float fw0 = g_fwd[(b*RR+0)*NN+tid], fw1 = g_fwd[(b*RR+1)*NN+tid];
    float fw2 = g_fwd[(b*RR+2)*NN+tid], fw3 = g_fwd[(b*RR+3)*NN+tid];

    float w0 = rm[0][0]*bw0 + rm[0][1]*rc0 + rm[0][2]*fw0;
    float w1 = rm[1][0]*bw1 + rm[1][1]*rc1 + rm[1][2]*fw1;
    float w2 = rm[2][0]*bw2 + rm[2][1]*rc2 + rm[2][2]*fw2;
    float w3 = rm[3][0]*bw3 + rm[3][1]*rc3 + rm[3][2]*fw3;
    g_rw[(b*RR+0)*NN+tid]=w0; g_rw[(b*RR+1)*NN+tid]=w1;
    g_rw[(b*RR+2)*NN+tid]=w2; g_rw[(b*RR+3)*NN+tid]=w3;
    rwn4[tid] = make_float4(w0,w1,w2,w3);
    __syncthreads();

    // rv: warp-partial over global M rows (coalesced), 8-warp reduce
    float a0x=0.f,a0y=0.f,a0z=0.f,a0w=0.f;   // w = l
    float a1x=0.f,a1y=0.f,a1z=0.f,a1w=0.f;   // w = l+32
    const float* Mb = g_M + b*NN*WD;
    #pragma unroll 4
    for (int q=0;q<32;q++){
        int n = wi*32 + q;
        float lv0 = Mb[n*WD + l];
        float lv1 = Mb[n*WD + l + 32];
        float4 rn = rwn4[n];
        a0x=fmaf(lv0,rn.x,a0x); a0y=fmaf(lv0,rn.y,a0y);
        a0z=fmaf(lv0,rn.z,a0z); a0w=fmaf(lv0,rn.w,a0w);
        a1x=fmaf(lv1,rn.x,a1x); a1y=fmaf(lv1,rn.y,a1y);
        a1z=fmaf(lv1,rn.z,a1z); a1w=fmaf(lv1,rn.w,a1w);
    }
    float* pb = partial + wi*256;
    pb[0*64+l]=a0x; pb[1*64+l]=a0y; pb[2*64+l]=a0z; pb[3*64+l]=a0w;
    pb[0*64+l+32]=a1x; pb[1*64+l+32]=a1y; pb[2*64+l+32]=a1z; pb[3*64+l+32]=a1w;
    __syncthreads();
    float sum = 0.f;
    #pragma unroll
    for (int g=0;g<8;g++) sum += partial[g*256 + tid];
    g_rv[b*(RR*WD) + tid] = sum;
}

// ---------------- K6 (final step only): out = pre_out + rv @ W_memout -----------
__global__ __launch_bounds__(256) void k_out(const float* __restrict__ Wm,
                                             float* __restrict__ out, int t){
    __shared__ __align__(16) float s[BB*RR*WD];
    int tid = threadIdx.x;
    for (int i=tid;i<BB*RR*WD;i+=256) s[i] = g_rv[i];
    __syncthreads();

    int kg = tid>>5, jl = tid&31;
    int j = blockIdx.x*32 + jl;
    const float* Wc = Wm + j;
    float acc[BB];
    #pragma unroll
    for (int b=0;b<BB;b++) acc[b]=0.f;
    int k0 = kg*32;
    #pragma unroll 2
    for (int kk=0; kk<32; kk+=4){
        int k = k0+kk;
        float w0 = Wc[(k+0)*OO], w1 = Wc[(k+1)*OO], w2 = Wc[(k+2)*OO], w3 = Wc[(k+3)*OO];
        #pragma unroll
        for (int b=0;b<BB;b++){
            float4 v = *reinterpret_cast<const float4*>(&s[b*(RR*WD)+k]);
            acc[b] = fmaf(v.x,w0, fmaf(v.y,w1, fmaf(v.z,w2, fmaf(v.w,w3, acc[b]))));
        }
    }
    __syncthreads();
    #pragma unroll
    for (int b=0;b<BB;b++) s[kg*512 + b*32 + jl] = acc[b];
    __syncthreads();
    for (int p=tid;p<512;p+=256){
        int b = p>>5, jj = p&31;
        int jo = blockIdx.x*32 + jj;
        float sum = g_po[b*OO + jo];
        #pragma unroll
        for (int g=0;g<8;g++) sum += s[g*512 + b*32 + jj];
        out[(t*BB + b)*OO + jo] = sum;
    }
}

// ---------------- launch --------------------------------------------------------
extern "C" void kernel_launch(void* const* d_in, const int* in_sizes, int n_in,
                              void* d_out, int out_size){
    const float* x  = (const float*)d_in[0];
    const float* Wh = (const float*)d_in[1];
    const float* bh = (const float*)d_in[2];
    const float* Wi = (const float*)d_in[3];
    const float* Wo = (const float*)d_in[4];
    const float* Wm = (const float*)d_in[5];
    float* out = (float*)d_out;

    const int smHid  = (BB*NIN + 16*256)*sizeof(float);  // 65536
    const int smProj = (BB*HH  + 16*256)*sizeof(float);  // 49152
    cudaFuncSetAttribute(k_hidout, cudaFuncAttributeMaxDynamicSharedMemorySize, smHid);
    cudaFuncSetAttribute(k_proj,   cudaFuncAttributeMaxDynamicSharedMemorySize, smProj);

    k_init<<<256,256>>>();
    for (int t=0;t<TT;t++){
        int par = t & 1;
        k_hidout <<<32,256,smHid>>>(x, Wh, bh, Wm, out, t);
        k_proj   <<<62,256,smProj>>>(Wo, Wi);
        k_wsim   <<<dim3(8,BB),256>>>();
        k_control<<<BB,256>>>(par);
        k_meml   <<<dim3(32,BB),256>>>(par);
        k_read   <<<BB,256>>>();
    }
    k_out<<<16,256>>>(Wm, out, TT-1);
}